// round 14
// baseline (speedup 1.0000x reference)
#include <cuda_runtime.h>
#include <cuda_fp16.h>
#include <math.h>
#include <stdint.h>

#define BB 4096
#define NU 6
#define IND 600
#define HH 600
#define VDD 400
#define KD 64
#define KP_PRE 1024   // 416 (xv) + 608 (hs)
#define KOFF_H 416
#define KP_H   608
#define KP_X   608
#define KP_CTX 2400
#define NP_BIG 2432
#define NP_H   640
#define NP_CVQ 2688   // 2400 cv | 32 pad | 128 ck | 128 cq
#define CK_OFF 2432
#define CQ_OFF 2560
#define NP_V   512

// ------------------------- device scratch -------------------------
__device__ __align__(16) float g_xk[BB * KD];
__device__ __align__(16) float g_qry[BB * NU * KD];
__device__ __align__(16) float g_scale[BB * NU];
__device__ __align__(16) float g_mask[BB * NU];
__device__ __align__(16) float g_hb[(size_t)BB * NU * HH];
__device__ int g_cnt[NU];
__device__ int g_posmap[BB * NU];
__device__ int g_blist[NU * BB];

__device__ __align__(16) __half g_xvh[(size_t)BB * VDD];
__device__ __align__(16) __half g_cvq[(size_t)BB * NU * NP_CVQ];
__device__ __align__(16) __half g_aph[(size_t)NU * BB * KP_PRE];
__device__ __align__(16) __half g_hbh[(size_t)NU * BB * KP_H];
__device__ __align__(16) __half g_cxc[(size_t)NU * BB * KP_CTX];
__device__ __align__(16) __half g_x16[(size_t)BB * KP_X];
__device__ __align__(16) __half g_w12h[(size_t)NU * NP_BIG * KP_PRE];
__device__ __align__(16) __half g_wcvq[(size_t)NU * NP_CVQ * KP_H];
__device__ __align__(16) __half g_w4h[(size_t)NU * NP_H * KP_CTX];
__device__ __align__(16) __half g_wv16[(size_t)NP_V * KP_X];

// ------------------------- helpers -------------------------
__device__ __forceinline__ uint32_t smem_u32(const void* p) {
    uint32_t a;
    asm("{ .reg .u64 t; cvta.to.shared.u64 t, %1; cvt.u32.u64 %0, t; }" : "=r"(a) : "l"(p));
    return a;
}
__device__ __forceinline__ void cp16(uint32_t dst, const void* src) {
    asm volatile("cp.async.cg.shared.global [%0], [%1], 16;\n" :: "r"(dst), "l"(src));
}
// fp16-accumulate MMA (double-rate)
__device__ __forceinline__ void mma16816h(uint32_t& d0, uint32_t& d1,
                                          const uint32_t* a, uint32_t b0, uint32_t b1,
                                          uint32_t c0, uint32_t c1) {
    asm volatile(
        "mma.sync.aligned.m16n8k16.row.col.f16.f16.f16.f16 "
        "{%0,%1}, {%2,%3,%4,%5}, {%6,%7}, {%8,%9};"
        : "=r"(d0), "=r"(d1)
        : "r"(a[0]), "r"(a[1]), "r"(a[2]), "r"(a[3]),
          "r"(b0), "r"(b1), "r"(c0), "r"(c1));
}
__device__ __forceinline__ void ldsm4(uint32_t* r, uint32_t addr) {
    asm volatile("ldmatrix.sync.aligned.m8n8.x4.shared.b16 {%0,%1,%2,%3}, [%4];"
                 : "=r"(r[0]), "=r"(r[1]), "=r"(r[2]), "=r"(r[3]) : "r"(addr));
}
__device__ __forceinline__ float sigf(float x) { return 1.f / (1.f + expf(-x)); }

#define TILE_B   10240
#define STAGE_B  20480
#define NSTAGE   4
#define SMEM_DYN (NSTAGE * STAGE_B + 16)

// ------------------------- HMMA GEMM (fp16-acc per K=32 chunk, fp32 master) -------------------------
// EPI 4: fp16 store.
// EPI 5: fused LSTM (gate-interleaved cols): Cv=hb(f32), S=mask, E1=cs, X2=cs_out, X3=hbh.
// EPI 6: compact-row scatter: Cv=hs_out, E1=hb, IB=blist, CT=cnt; C[b,z] = acc + hb[b,z].
template <int EPI>
__global__ void __launch_bounds__(256, 2)
hmma_gemm(const __half* __restrict__ A, long long sA, int Kpad,
          const __half* __restrict__ B, long long sB,
          void* __restrict__ Cv, int ldc, int sC, int Nreal,
          const float* __restrict__ S,
          const float* __restrict__ E1,
          float* __restrict__ X2, __half* __restrict__ X3,
          const int* __restrict__ IB, const int* __restrict__ CT)
{
    extern __shared__ __align__(16) char dsm[];
    const uint32_t tiles_u32 = smem_u32(dsm);

    const int tid = threadIdx.x;
    const int wid = tid >> 5, lane = tid & 31;
    const int wm = wid >> 1, wn = wid & 1;        // 4 x 2 warps, 32x64 each
    const int g = lane >> 2, t = lane & 3;
    const int lane16 = lane & 15, lanehi = lane >> 4;

    const int z = blockIdx.z, m0 = blockIdx.y * 128, n0 = blockIdx.x * 128;
    int cntz = 0;
    if (EPI == 6) {
        cntz = CT[z];
        if (m0 >= cntz) return;
    }
    const __half* Az = A + (size_t)z * sA + (size_t)m0 * Kpad;
    const __half* Bz = B + (size_t)z * sB + (size_t)n0 * Kpad;

    const int nch = Kpad >> 5;   // BK = 32

    const int idx0 = tid * 2, idx1 = tid * 2 + 1;
    const int r_0 = idx0 >> 2, c_0 = idx0 & 3;
    const int r_1 = idx1 >> 2, c_1 = idx1 & 3;

    auto load_chunk = [&](int kc) {
        uint32_t sb = tiles_u32 + (uint32_t)(kc & 3) * STAGE_B;
        int k0 = kc << 5;
        cp16(sb + r_0 * 80 + c_0 * 16, Az + (size_t)r_0 * Kpad + k0 + c_0 * 8);
        cp16(sb + r_1 * 80 + c_1 * 16, Az + (size_t)r_1 * Kpad + k0 + c_1 * 8);
        cp16(sb + TILE_B + r_0 * 80 + c_0 * 16, Bz + (size_t)r_0 * Kpad + k0 + c_0 * 8);
        cp16(sb + TILE_B + r_1 * 80 + c_1 * 16, Bz + (size_t)r_1 * Kpad + k0 + c_1 * 8);
    };

    float acc[2][8][4];
#pragma unroll
    for (int a = 0; a < 2; a++)
#pragma unroll
        for (int b = 0; b < 8; b++)
#pragma unroll
            for (int c = 0; c < 4; c++) acc[a][b][c] = 0.f;

    const uint32_t aOff = (uint32_t)((wm * 32 + lane16) * 80 + lanehi * 16);
    const uint32_t bOff = (uint32_t)(TILE_B + (wn * 64 + lane16) * 80 + lanehi * 16);

    load_chunk(0);
    asm volatile("cp.async.commit_group;" ::: "memory");
    load_chunk(1);
    asm volatile("cp.async.commit_group;" ::: "memory");
    load_chunk(2);
    asm volatile("cp.async.commit_group;" ::: "memory");

    for (int kc = 0; kc < nch; kc++) {
        asm volatile("cp.async.wait_group 2;" ::: "memory");
        __syncthreads();
        if (kc + 3 < nch) load_chunk(kc + 3);
        asm volatile("cp.async.commit_group;" ::: "memory");

        const uint32_t sb = tiles_u32 + (uint32_t)(kc & 3) * STAGE_B;

        // A fragments for both K16 halves of this K32 chunk
        uint32_t afr[2][2][4];
#pragma unroll
        for (int mt = 0; mt < 2; mt++) {
            ldsm4(afr[mt][0], sb + aOff + (uint32_t)(mt * 16 * 80));
            ldsm4(afr[mt][1], sb + aOff + (uint32_t)(mt * 16 * 80) + 32);
        }
#pragma unroll
        for (int nt2 = 0; nt2 < 4; nt2++) {
            uint32_t b0[4], b1[4];
            ldsm4(b0, sb + bOff + (uint32_t)(nt2 * 16 * 80));
            ldsm4(b1, sb + bOff + (uint32_t)(nt2 * 16 * 80) + 32);
#pragma unroll
            for (int mt = 0; mt < 2; mt++) {
#pragma unroll
                for (int nh = 0; nh < 2; nh++) {
                    uint32_t h0, h1;
                    mma16816h(h0, h1, afr[mt][0], b0[nh], b0[nh + 2], 0u, 0u);
                    mma16816h(h0, h1, afr[mt][1], b1[nh], b1[nh + 2], h0, h1);
                    float* ac = acc[mt][nt2 * 2 + nh];
                    float2 lo = __half22float2(*(__half2*)&h0);
                    float2 hi = __half22float2(*(__half2*)&h1);
                    ac[0] += lo.x; ac[1] += lo.y; ac[2] += hi.x; ac[3] += hi.y;
                }
            }
        }
    }

    // ----- epilogue -----
    if (EPI == 5) {
        float* hb = (float*)Cv;
#pragma unroll
        for (int mt = 0; mt < 2; mt++) {
            const int b0r = m0 + wm * 32 + mt * 16 + g;
            const int b1r = b0r + 8;
#pragma unroll
            for (int nt = 0; nt < 8; nt++) {
                float i0 = acc[mt][nt][0], f0 = acc[mt][nt][1];
                float i1 = acc[mt][nt][2], f1 = acc[mt][nt][3];
                float o0 = __shfl_xor_sync(~0u, i0, 1);
                float g0 = __shfl_xor_sync(~0u, f0, 1);
                float o1 = __shfl_xor_sync(~0u, i1, 1);
                float g1 = __shfl_xor_sync(~0u, f1, 1);
                if ((t & 1) == 0) {
                    const int c0 = n0 + wn * 64 + nt * 8 + 2 * t;
                    const int j = c0 >> 2;
                    if (j < HH) {
                        size_t i00 = ((size_t)b0r * NU + z) * HH + j;
                        size_t i10 = ((size_t)b1r * NU + z) * HH + j;
                        size_t h00 = ((size_t)z * BB + b0r) * KP_H + j;
                        size_t h10 = ((size_t)z * BB + b1r) * KP_H + j;
                        float mk0 = S[b0r * NU + z], mk1 = S[b1r * NU + z];
                        float cp0 = E1[i00], cp1 = E1[i10];
                        float c0v = cp0 * sigf(f0) + sigf(i0) * tanhf(g0);
                        float c1v = cp1 * sigf(f1) + sigf(i1) * tanhf(g1);
                        float h0v = sigf(o0) * tanhf(c0v);
                        float h1v = sigf(o1) * tanhf(c1v);
                        hb[i00] = h0v;  hb[i10] = h1v;
                        X2[i00] = (mk0 > 0.5f) ? c0v : cp0;
                        X2[i10] = (mk1 > 0.5f) ? c1v : cp1;
                        X3[h00] = __float2half_rn(h0v);
                        X3[h10] = __float2half_rn(h1v);
                    }
                }
            }
        }
        return;
    }

    if (EPI == 6) {
        float* out = (float*)Cv;
#pragma unroll
        for (int mt = 0; mt < 2; mt++) {
            const int r0 = m0 + wm * 32 + mt * 16 + g;
            const int r1 = r0 + 8;
            const bool v0 = r0 < cntz, v1 = r1 < cntz;
            const int b0 = v0 ? IB[z * BB + r0] : 0;
            const int b1 = v1 ? IB[z * BB + r1] : 0;
            const size_t base0 = ((size_t)b0 * NU + z) * HH;
            const size_t base1 = ((size_t)b1 * NU + z) * HH;
#pragma unroll
            for (int nt = 0; nt < 8; nt++) {
                const int n = n0 + wn * 64 + nt * 8 + 2 * t;
                if (n < Nreal) {
                    if (v0) {
                        float2 o = *(const float2*)(E1 + base0 + n);
                        float2 v = make_float2(acc[mt][nt][0] + o.x, acc[mt][nt][1] + o.y);
                        *(float2*)(out + base0 + n) = v;
                    }
                    if (v1) {
                        float2 o = *(const float2*)(E1 + base1 + n);
                        float2 v = make_float2(acc[mt][nt][2] + o.x, acc[mt][nt][3] + o.y);
                        *(float2*)(out + base1 + n) = v;
                    }
                }
            }
        }
        return;
    }

    // EPI 4: fp16 store
#pragma unroll
    for (int mt = 0; mt < 2; mt++) {
        const int r0 = m0 + wm * 32 + mt * 16 + g;
        const int r1 = r0 + 8;
        __half* h0row = (__half*)Cv + (size_t)r0 * ldc + (size_t)z * sC;
        __half* h1row = (__half*)Cv + (size_t)r1 * ldc + (size_t)z * sC;
#pragma unroll
        for (int nt = 0; nt < 8; nt++) {
            const int n = n0 + wn * 64 + nt * 8 + 2 * t;
            if (n < Nreal) {
                *(__half2*)(h0row + n) = __floats2half2_rn(acc[mt][nt][0], acc[mt][nt][1]);
                *(__half2*)(h1row + n) = __floats2half2_rn(acc[mt][nt][2], acc[mt][nt][3]);
            }
        }
    }
}

// ------------------------- unified xk + qry SIMT GEMM (fp32 mask path) -------------------------
__global__ void __launch_bounds__(256)
xkqry_simt(const float* __restrict__ x, const float* __restrict__ hs,
           const float* __restrict__ Wk, const float* __restrict__ Wq,
           float* __restrict__ xk, float* __restrict__ qry)
{
    __shared__ __align__(16) float As[8][64];
    __shared__ __align__(16) float Bs[8][64];
    const int z = blockIdx.z;
    const float* A; int lda; const float* W; float* C; int ldc;
    if (z < NU) {
        A = hs + z * HH; lda = NU * HH;
        W = Wq + (size_t)z * HH * KD;
        C = qry + z * KD; ldc = NU * KD;
    } else {
        A = x; lda = IND; W = Wk; C = xk; ldc = KD;
    }
    const int tid = threadIdx.x;
    const int tx = tid & 15, ty = tid >> 4;
    const int m0 = blockIdx.y * 64;
    float acc[4][4];
#pragma unroll
    for (int i = 0; i < 4; i++)
#pragma unroll
        for (int j = 0; j < 4; j++) acc[i][j] = 0.f;
    const int ar = tid >> 1, ac = (tid & 1) * 4;
    const int wr = tid >> 4, wc = (tid & 15) * 4;
    for (int k0 = 0; k0 < 600; k0 += 8) {
        __syncthreads();
        if (ar < 64) {
            float4 v = *(const float4*)(A + (size_t)(m0 + ar) * lda + k0 + ac);
            As[ac][ar] = v.x; As[ac + 1][ar] = v.y; As[ac + 2][ar] = v.z; As[ac + 3][ar] = v.w;
        }
        if (wr < 8) {
            float4 v = *(const float4*)(W + (size_t)(k0 + wr) * KD + wc);
            *(float4*)&Bs[wr][wc] = v;
        }
        __syncthreads();
#pragma unroll
        for (int kk = 0; kk < 8; kk++) {
            float af[4], bf[4];
            *(float4*)af = *(const float4*)&As[kk][ty * 4];
            *(float4*)bf = *(const float4*)&Bs[kk][tx * 4];
#pragma unroll
            for (int i = 0; i < 4; i++)
#pragma unroll
                for (int j = 0; j < 4; j++) acc[i][j] = fmaf(af[i], bf[j], acc[i][j]);
        }
    }
#pragma unroll
    for (int i = 0; i < 4; i++) {
        float4 v;
        v.x = acc[i][0]; v.y = acc[i][1]; v.z = acc[i][2]; v.w = acc[i][3];
        *(float4*)(C + (size_t)(m0 + ty * 4 + i) * ldc + tx * 4) = v;
    }
}

// ------------------- merged weight transpose (all segments, one launch) -------------------
__global__ void __launch_bounds__(256)
wtrans_all(const float* __restrict__ Wi2h, const float* __restrict__ Wh2h,
           const float* __restrict__ Wcv, const float* __restrict__ Wco,
           const float* __restrict__ Wck, const float* __restrict__ Wcq,
           const float* __restrict__ Wv,
           __half* __restrict__ w12h, __half* __restrict__ wcvq, __half* __restrict__ w4h,
           __half* __restrict__ wv16)
{
    __shared__ float tt[64][33];
    int L = blockIdx.x;
    const float* W; __half* Oh;
    int Kreal, Nreal, Kp, Np, koff, perm, klim, gx, gy;
    if (L < 3150)       { W = Wi2h; Oh = w12h; Kreal = 400;  Nreal = 2400; Kp = KP_PRE; Np = NP_BIG; koff = 0;      perm = 1; klim = KOFF_H; gx = 7;  gy = 75; }
    else if (L < 7650)  { L -= 3150;  W = Wh2h; Oh = w12h; Kreal = 600;  Nreal = 2400; Kp = KP_PRE; Np = NP_BIG; koff = KOFF_H; perm = 1; klim = 608;  gx = 10; gy = 75; }
    else if (L < 12150) { L -= 7650;  W = Wcv;  Oh = wcvq; Kreal = 600;  Nreal = 2400; Kp = KP_H;   Np = NP_CVQ; koff = 0;      perm = 0; klim = 608;  gx = 10; gy = 75; }
    else if (L < 16482) { L -= 12150; W = Wco;  Oh = w4h;  Kreal = 2400; Nreal = 600;  Kp = KP_CTX; Np = NP_H;   koff = 0;      perm = 0; klim = 2400; gx = 38; gy = 19; }
    else if (L < 16722) { L -= 16482; W = Wck;  Oh = wcvq + (size_t)CK_OFF * KP_H; Kreal = 600; Nreal = 128; Kp = KP_H; Np = NP_CVQ; koff = 0; perm = 0; klim = 608; gx = 10; gy = 4; }
    else if (L < 16962) { L -= 16722; W = Wcq;  Oh = wcvq + (size_t)CQ_OFF * KP_H; Kreal = 600; Nreal = 128; Kp = KP_H; Np = NP_CVQ; koff = 0; perm = 0; klim = 608; gx = 10; gy = 4; }
    else                { L -= 16962; W = Wv;   Oh = wv16; Kreal = 600;  Nreal = 400;  Kp = KP_X;   Np = NP_V;   koff = 0;      perm = 0; klim = 608;  gx = 10; gy = 13; }
    const int seg = gx * gy;
    const int u = L / seg, rem = L % seg;
    const int kb = (rem % gx) * 64, nb = (rem / gx) * 32;
    const float* Wu = W + (size_t)u * Kreal * Nreal;
    const int tx = threadIdx.x & 31, ty = threadIdx.x >> 5;  // 32 x 8
#pragma unroll
    for (int yy = ty; yy < 64; yy += 8) {
        int k = kb + yy, n = nb + tx;
        tt[yy][tx] = (k < Kreal && n < Nreal) ? Wu[(size_t)k * Nreal + n] : 0.f;
    }
    __syncthreads();
    __half* OhU = Oh + (size_t)u * Np * Kp + (size_t)koff;
#pragma unroll
    for (int yy = ty; yy < 32; yy += 8) {
        int n = nb + yy;
        int k = kb + 2 * tx;
        if (k + 1 < klim) {
            int pn = perm ? ((n % 600) * 4 + n / 600) : n;
            __half2 v = __floats2half2_rn(tt[2 * tx][yy], tt[2 * tx + 1][yy]);
            *(__half2*)(OhU + (size_t)pn * Kp + k) = v;
        }
    }
}

// ------------------- x -> fp16 padded -------------------
__global__ void conv_x(const float* __restrict__ x, __half* __restrict__ o)
{
    int idx = blockIdx.x * blockDim.x + threadIdx.x;
    if (idx >= BB * KP_X) return;
    int k = idx % KP_X, b = idx / KP_X;
    o[idx] = __float2half_rn(k < IND ? x[(size_t)b * IND + k] : 0.f);
}

// ------------------- A_pre = [scale*xv | hs] fp16 (half2 vectorized) -------------------
__global__ void conv_pre(const __half* __restrict__ xv, const float* __restrict__ hs,
                         const float* __restrict__ scale, __half* __restrict__ oh)
{
    size_t idx = (size_t)blockIdx.x * blockDim.x + threadIdx.x;
    const size_t HALF_K = KP_PRE / 2;
    if (idx >= (size_t)NU * BB * HALF_K) return;
    int k = (int)(idx % HALF_K) * 2;
    int b = (int)((idx / HALF_K) % BB);
    int u = (int)(idx / (HALF_K * BB));
    float v0 = 0.f, v1 = 0.f;
    if (k < VDD) {
        float sc = scale[b * NU + u];
        __half2 xp = *(const __half2*)(xv + (size_t)b * VDD + k);
        float2 xf = __half22float2(xp);
        v0 = sc * xf.x; v1 = sc * xf.y;
    } else if (k >= KOFF_H && k < KOFF_H + HH) {
        float2 hf = *(const float2*)(hs + (size_t)b * (NU * HH) + u * HH + (k - KOFF_H));
        v0 = hf.x; v1 = hf.y;
    }
    *(__half2*)(oh + idx * 2) = __floats2half2_rn(v0, v1);
}

// ------------------- zero counters -------------------
__global__ void zero_cnt(int* cnt)
{
    if (threadIdx.x < NU) cnt[threadIdx.x] = 0;
}

// ------------------- score + top-k + compaction lists -------------------
__global__ void score_topk(const float* __restrict__ qry, const float* __restrict__ xk,
                           float* __restrict__ scale, float* __restrict__ mask,
                           int* __restrict__ cnt, int* __restrict__ posmap,
                           int* __restrict__ blist)
{
    int gw = (blockIdx.x * blockDim.x + threadIdx.x) >> 5;
    int lane = threadIdx.x & 31;
    if (gw >= BB) return;
    int b = gw;
    float xk0 = xk[b * 64 + lane], xk1 = xk[b * 64 + 32 + lane];
    float s[NU];
#pragma unroll
    for (int u = 0; u < NU; u++) {
        const float* q = qry + b * (NU * 64) + u * 64;
        float v = q[lane] * xk0 + q[32 + lane] * xk1;
#pragma unroll
        for (int o = 16; o; o >>= 1) v += __shfl_xor_sync(~0u, v, o);
        s[u] = v * 0.125f;
    }
    if (lane == 0) {
#pragma unroll
        for (int u = 0; u < NU; u++) {
            int c = 0;
#pragma unroll
            for (int v = 0; v < NU; v++)
                if (s[v] > s[u] || (s[v] == s[u] && v < u)) c++;
            float m = (c < 4) ? 1.f : 0.f;
            mask[b * NU + u] = m;
            scale[b * NU + u] = m / (1.f + expf(-s[u]));
            if (m > 0.5f) {
                int p = atomicAdd(&cnt[u], 1);
                blist[u * BB + p] = b;
                posmap[b * NU + u] = p;
            } else {
                posmap[b * NU + u] = -1;
            }
        }
    }
}

// ------------------- comm attention + inactive hs copy (half2/float4 vectorized) -------------------
__global__ void __launch_bounds__(256)
comm_attn(const __half* __restrict__ cvq, const float* __restrict__ mask,
          const int* __restrict__ posmap, const float* __restrict__ hs,
          float* __restrict__ hs_out, __half* __restrict__ cxc)
{
    int b = blockIdx.x;
    __shared__ float s_ck[NU * 128], s_cq[NU * 128];
    __shared__ float s_sc[NU][4][NU];
    __shared__ float s_pr[NU][4][8];
    __shared__ int s_pos[NU];
    int t = threadIdx.x;
    const __half* base = cvq + (size_t)b * (NU * NP_CVQ);
    for (int i = t; i < NU * 64; i += 256) {
        int m = i >> 6, c = (i & 63) * 2;
        float2 k2 = __half22float2(*(const __half2*)(base + m * NP_CVQ + CK_OFF + c));
        float2 q2 = __half22float2(*(const __half2*)(base + m * NP_CVQ + CQ_OFF + c));
        s_ck[m * 128 + c] = k2.x; s_ck[m * 128 + c + 1] = k2.y;
        s_cq[m * 128 + c] = q2.x; s_cq[m * 128 + c + 1] = q2.y;
    }
    if (t < NU) s_pos[t] = posmap[b * NU + t];
    __syncthreads();

    int w = t >> 5, lane = t & 31;
    for (int p = w; p < NU * 4 * NU; p += 8) {
        int uq = p / 24, rem = p % 24, hh = rem / 6, m = rem % 6;
        float v = s_cq[uq * 128 + hh * 32 + lane] * s_ck[m * 128 + hh * 32 + lane];
#pragma unroll
        for (int o = 16; o; o >>= 1) v += __shfl_xor_sync(~0u, v, o);
        if (lane == 0) s_sc[uq][hh][m] = v * 0.17677669529663687f;
    }
    __syncthreads();

    if (t < NU * 4) {
        int uq = t >> 2, hh = t & 3;
        float mx = -1e30f;
#pragma unroll
        for (int m = 0; m < NU; m++) mx = fmaxf(mx, s_sc[uq][hh][m]);
        float e[NU], sum = 0.f;
#pragma unroll
        for (int m = 0; m < NU; m++) { e[m] = expf(s_sc[uq][hh][m] - mx); sum += e[m]; }
        float inv = mask[b * NU + uq] / sum;
#pragma unroll
        for (int m = 0; m < NU; m++) s_pr[uq][hh][m] = e[m] * inv;
    }
    __syncthreads();

    for (int i2 = t; i2 < 1200; i2 += 256) {
        int i = i2 * 2;
        int hh = i / 600;
        float2 c[NU];
#pragma unroll
        for (int m = 0; m < NU; m++)
            c[m] = __half22float2(*(const __half2*)(base + m * NP_CVQ + i));
#pragma unroll
        for (int uq = 0; uq < NU; uq++) {
            int pos = s_pos[uq];
            if (pos >= 0) {
                float a0 = 0.f, a1 = 0.f;
#pragma unroll
                for (int m = 0; m < NU; m++) {
                    float pr = s_pr[uq][hh][m];
                    a0 += pr * c[m].x;
                    a1 += pr * c[m].y;
                }
                *(__half2*)(cxc + ((size_t)uq * BB + pos) * KP_CTX + i) =
                    __floats2half2_rn(a0, a1);
            }
        }
    }

#pragma unroll
    for (int uq = 0; uq < NU; uq++) {
        if (s_pos[uq] < 0) {
            const float4* src = (const float4*)(hs + ((size_t)b * NU + uq) * HH);
            float4* dst = (float4*)(hs_out + ((size_t)b * NU + uq) * HH);
            for (int i = t; i < 150; i += 256) dst[i] = src[i];
        }
    }
}

// ------------------------- launch -------------------------
extern "C" void kernel_launch(void* const* d_in, const int* in_sizes, int n_in,
                              void* d_out, int out_size)
{
    const float* x    = (const float*)d_in[0];
    const float* hs   = (const float*)d_in[1];
    const float* cs   = (const float*)d_in[2];
    const float* Wk   = (const float*)d_in[3];
    const float* Wv   = (const float*)d_in[4];
    const float* Wq   = (const float*)d_in[5];
    const float* Wi2h = (const float*)d_in[6];
    const float* Wh2h = (const float*)d_in[7];
    const float* Wck  = (const float*)d_in[8];
    const float* Wcq  = (const float*)d_in[9];
    const float* Wcv  = (const float*)d_in[10];
    const float* Wco  = (const float*)d_in[11];

    float* hs_out = (float*)d_out;
    float* cs_out = hs_out + (size_t)BB * NU * HH;

    float *xk, *qry, *scale, *mask, *hb;
    int *cnt, *posmap, *blist;
    __half *xvh, *cvq, *aph, *hbh, *cxc, *x16, *w12h, *wcvq, *w4h, *wv16;
    cudaGetSymbolAddress((void**)&xk, g_xk);
    cudaGetSymbolAddress((void**)&qry, g_qry);     cudaGetSymbolAddress((void**)&scale, g_scale);
    cudaGetSymbolAddress((void**)&mask, g_mask);   cudaGetSymbolAddress((void**)&hb, g_hb);
    cudaGetSymbolAddress((void**)&cnt, g_cnt);
    cudaGetSymbolAddress((void**)&posmap, g_posmap);
    cudaGetSymbolAddress((void**)&blist, g_blist);
    cudaGetSymbolAddress((void**)&xvh, g_xvh);
    cudaGetSymbolAddress((void**)&cvq, g_cvq);
    cudaGetSymbolAddress((void**)&aph, g_aph);
    cudaGetSymbolAddress((void**)&hbh, g_hbh);
    cudaGetSymbolAddress((void**)&cxc, g_cxc);
    cudaGetSymbolAddress((void**)&x16, g_x16);
    cudaGetSymbolAddress((void**)&w12h, g_w12h);
    cudaGetSymbolAddress((void**)&wcvq, g_wcvq);
    cudaGetSymbolAddress((void**)&w4h, g_w4h);
    cudaGetSymbolAddress((void**)&wv16, g_wv16);

    cudaFuncSetAttribute(hmma_gemm<4>, cudaFuncAttributeMaxDynamicSharedMemorySize, SMEM_DYN);
    cudaFuncSetAttribute(hmma_gemm<5>, cudaFuncAttributeMaxDynamicSharedMemorySize, SMEM_DYN);
    cudaFuncSetAttribute(hmma_gemm<6>, cudaFuncAttributeMaxDynamicSharedMemorySize, SMEM_DYN);

    static cudaStream_t s_side = nullptr;
    static cudaEvent_t s_fork = nullptr, s_join = nullptr;
    if (!s_side) {
        cudaStreamCreateWithFlags(&s_side, cudaStreamNonBlocking);
        cudaEventCreateWithFlags(&s_fork, cudaEventDisableTiming);
        cudaEventCreateWithFlags(&s_join, cudaEventDisableTiming);
    }

    cudaEventRecord(s_fork, (cudaStream_t)0);
    cudaStreamWaitEvent(s_side, s_fork, 0);

    zero_cnt<<<1, 32, 0, s_side>>>(cnt);
    xkqry_simt<<<dim3(1, 64, 7), 256, 0, s_side>>>(x, hs, Wk, Wq, xk, qry);
    score_topk<<<(BB * 32 + 255) / 256, 256, 0, s_side>>>(qry, xk, scale, mask, cnt, posmap, blist);
    cudaEventRecord(s_join, s_side);

    wtrans_all<<<17092, 256>>>(Wi2h, Wh2h, Wcv, Wco, Wck, Wcq, Wv,
                               w12h, wcvq, w4h, wv16);
    conv_x<<<(BB * KP_X + 255) / 256, 256>>>(x, x16);
    hmma_gemm<4><<<dim3(4, 32, 1), 256, SMEM_DYN>>>(
        x16, 0LL, KP_X, wv16, 0LL, xvh, VDD, 0, VDD,
        nullptr, nullptr, nullptr, nullptr, nullptr, nullptr);

    cudaStreamWaitEvent((cudaStream_t)0, s_join, 0);

    conv_pre<<<(int)(((size_t)NU * BB * (KP_PRE / 2) + 255) / 256), 256>>>(xvh, hs, scale, aph);

    // preact GEMM + fused LSTM epilogue -> hb, hbh, cs_out
    hmma_gemm<5><<<dim3(19, 32, NU), 256, SMEM_DYN>>>(
        aph, (long long)BB * KP_PRE, KP_PRE, w12h, (long long)NP_BIG * KP_PRE,
        hb, 0, 0, 2400, mask, cs, cs_out, hbh, nullptr, nullptr);

    // cv | ck | cq combined (N=2688, fp16 out)
    hmma_gemm<4><<<dim3(21, 32, NU), 256, SMEM_DYN>>>(
        hbh, (long long)BB * KP_H, KP_H, wcvq, (long long)NP_CVQ * KP_H,
        cvq, NU * NP_CVQ, NP_CVQ, NP_CVQ, nullptr, nullptr, nullptr, nullptr, nullptr, nullptr);

    // comm attention (+ inactive hs copy)
    comm_attn<<<BB, 256>>>(cvq, mask, posmap, hs, hs_out, cxc);

    // hs_out (active rows only) = ctx_compact @ Wco + hb, scattered by blist
    hmma_gemm<6><<<dim3(5, 32, NU), 256, SMEM_DYN>>>(
        cxc, (long long)BB * KP_CTX, KP_CTX, w4h, (long long)NP_H * KP_CTX,
        hs_out, 0, 0, HH, nullptr, hb, nullptr, nullptr, blist, cnt);

    (void)in_sizes; (void)n_in; (void)out_size;
}

// round 15
// speedup vs baseline: 1.2436x; 1.2436x over previous
#include <cuda_runtime.h>
#include <cuda_fp16.h>
#include <math.h>
#include <stdint.h>

#define BB 4096
#define NU 6
#define IND 600
#define HH 600
#define VDD 400
#define KD 64
#define KP_PRE 1024   // 416 (xv) + 608 (hs)
#define KOFF_H 416
#define KP_H   608
#define KP_X   608
#define KP_CTX 2400
#define NP_BIG 2432
#define NP_H   640
#define NP_CVQ 2688   // 2400 cv | 32 pad | 128 ck | 128 cq
#define CK_OFF 2432
#define CQ_OFF 2560
#define NP_V   512

// ------------------------- device scratch -------------------------
__device__ __align__(16) float g_xk[BB * KD];
__device__ __align__(16) float g_qry[BB * NU * KD];
__device__ __align__(16) float g_scale[BB * NU];
__device__ __align__(16) float g_mask[BB * NU];
__device__ __align__(16) float g_hb[(size_t)BB * NU * HH];
__device__ int g_cnt[NU];
__device__ int g_posmap[BB * NU];
__device__ int g_blist[NU * BB];

__device__ __align__(16) __half g_xvh[(size_t)BB * VDD];
__device__ __align__(16) __half g_cvq[(size_t)BB * NU * NP_CVQ];
__device__ __align__(16) __half g_aph[(size_t)NU * BB * KP_PRE];
__device__ __align__(16) __half g_hbh[(size_t)NU * BB * KP_H];
__device__ __align__(16) __half g_cxc[(size_t)NU * BB * KP_CTX];
__device__ __align__(16) __half g_x16[(size_t)BB * KP_X];
__device__ __align__(16) __half g_w12h[(size_t)NU * NP_BIG * KP_PRE];
__device__ __align__(16) __half g_wcvq[(size_t)NU * NP_CVQ * KP_H];
__device__ __align__(16) __half g_w4h[(size_t)NU * NP_H * KP_CTX];
__device__ __align__(16) __half g_wv16[(size_t)NP_V * KP_X];

// ------------------------- helpers -------------------------
__device__ __forceinline__ uint32_t smem_u32(const void* p) {
    uint32_t a;
    asm("{ .reg .u64 t; cvta.to.shared.u64 t, %1; cvt.u32.u64 %0, t; }" : "=r"(a) : "l"(p));
    return a;
}
__device__ __forceinline__ void cp16(uint32_t dst, const void* src) {
    asm volatile("cp.async.cg.shared.global [%0], [%1], 16;\n" :: "r"(dst), "l"(src));
}
__device__ __forceinline__ void mma16816(float* c, const uint32_t* a, uint32_t b0, uint32_t b1) {
    asm volatile(
        "mma.sync.aligned.m16n8k16.row.col.f32.f16.f16.f32 "
        "{%0,%1,%2,%3}, {%4,%5,%6,%7}, {%8,%9}, {%0,%1,%2,%3};"
        : "+f"(c[0]), "+f"(c[1]), "+f"(c[2]), "+f"(c[3])
        : "r"(a[0]), "r"(a[1]), "r"(a[2]), "r"(a[3]), "r"(b0), "r"(b1));
}
__device__ __forceinline__ void ldsm4(uint32_t* r, uint32_t addr) {
    asm volatile("ldmatrix.sync.aligned.m8n8.x4.shared.b16 {%0,%1,%2,%3}, [%4];"
                 : "=r"(r[0]), "=r"(r[1]), "=r"(r[2]), "=r"(r[3]) : "r"(addr));
}
__device__ __forceinline__ float sigf(float x) { return 1.f / (1.f + expf(-x)); }

#define TILE_B   10240
#define STAGE_B  20480
#define NSTAGE   4
#define SMEM_DYN (NSTAGE * STAGE_B + 16)

// ------------------------- HMMA GEMM (fp16, ldmatrix, 4-stage) -------------------------
// EPI 4: fp16 store.
// EPI 5: fused LSTM (gate-interleaved cols): Cv=hb(f32), S=mask, E1=cs, X2=cs_out, X3=hbh.
// EPI 6: compact-row scatter: Cv=hs_out, E1=hb, IB=blist, CT=cnt; C[b,z] = acc + hb[b,z].
template <int EPI>
__global__ void __launch_bounds__(256, 2)
hmma_gemm(const __half* __restrict__ A, long long sA, int Kpad,
          const __half* __restrict__ B, long long sB,
          void* __restrict__ Cv, int ldc, int sC, int Nreal,
          const float* __restrict__ S,
          const float* __restrict__ E1,
          float* __restrict__ X2, __half* __restrict__ X3,
          const int* __restrict__ IB, const int* __restrict__ CT)
{
    extern __shared__ __align__(16) char dsm[];
    const uint32_t tiles_u32 = smem_u32(dsm);

    const int tid = threadIdx.x;
    const int wid = tid >> 5, lane = tid & 31;
    const int wm = wid >> 1, wn = wid & 1;        // 4 x 2 warps, 32x64 each
    const int g = lane >> 2, t = lane & 3;
    const int lane16 = lane & 15, lanehi = lane >> 4;

    const int z = blockIdx.z, m0 = blockIdx.y * 128, n0 = blockIdx.x * 128;
    int cntz = 0;
    if (EPI == 6) {
        cntz = CT[z];
        if (m0 >= cntz) return;
    }
    const __half* Az = A + (size_t)z * sA + (size_t)m0 * Kpad;
    const __half* Bz = B + (size_t)z * sB + (size_t)n0 * Kpad;

    const int nch = Kpad >> 5;   // BK = 32

    const int idx0 = tid * 2, idx1 = tid * 2 + 1;
    const int r_0 = idx0 >> 2, c_0 = idx0 & 3;
    const int r_1 = idx1 >> 2, c_1 = idx1 & 3;

    auto load_chunk = [&](int kc) {
        uint32_t sb = tiles_u32 + (uint32_t)(kc & 3) * STAGE_B;
        int k0 = kc << 5;
        cp16(sb + r_0 * 80 + c_0 * 16, Az + (size_t)r_0 * Kpad + k0 + c_0 * 8);
        cp16(sb + r_1 * 80 + c_1 * 16, Az + (size_t)r_1 * Kpad + k0 + c_1 * 8);
        cp16(sb + TILE_B + r_0 * 80 + c_0 * 16, Bz + (size_t)r_0 * Kpad + k0 + c_0 * 8);
        cp16(sb + TILE_B + r_1 * 80 + c_1 * 16, Bz + (size_t)r_1 * Kpad + k0 + c_1 * 8);
    };

    float acc[2][8][4];
#pragma unroll
    for (int a = 0; a < 2; a++)
#pragma unroll
        for (int b = 0; b < 8; b++)
#pragma unroll
            for (int c = 0; c < 4; c++) acc[a][b][c] = 0.f;

    const uint32_t aOff = (uint32_t)((wm * 32 + lane16) * 80 + lanehi * 16);
    const uint32_t bOff = (uint32_t)(TILE_B + (wn * 64 + lane16) * 80 + lanehi * 16);

    load_chunk(0);
    asm volatile("cp.async.commit_group;" ::: "memory");
    load_chunk(1);
    asm volatile("cp.async.commit_group;" ::: "memory");
    load_chunk(2);
    asm volatile("cp.async.commit_group;" ::: "memory");

    for (int kc = 0; kc < nch; kc++) {
        asm volatile("cp.async.wait_group 2;" ::: "memory");
        __syncthreads();
        if (kc + 3 < nch) load_chunk(kc + 3);
        asm volatile("cp.async.commit_group;" ::: "memory");

        const uint32_t sb = tiles_u32 + (uint32_t)(kc & 3) * STAGE_B;
#pragma unroll
        for (int s16 = 0; s16 < 2; s16++) {
            const uint32_t ko = (uint32_t)(s16 * 32);
            uint32_t a0[4], a1[4];
            ldsm4(a0, sb + aOff + ko);
            ldsm4(a1, sb + aOff + 16 * 80 + ko);
#pragma unroll
            for (int nt2 = 0; nt2 < 4; nt2++) {
                uint32_t bb[4];
                ldsm4(bb, sb + bOff + (uint32_t)(nt2 * 16 * 80) + ko);
                mma16816(acc[0][nt2 * 2],     a0, bb[0], bb[2]);
                mma16816(acc[0][nt2 * 2 + 1], a0, bb[1], bb[3]);
                mma16816(acc[1][nt2 * 2],     a1, bb[0], bb[2]);
                mma16816(acc[1][nt2 * 2 + 1], a1, bb[1], bb[3]);
            }
        }
    }

    // ----- epilogue -----
    if (EPI == 5) {
        float* hb = (float*)Cv;
#pragma unroll
        for (int mt = 0; mt < 2; mt++) {
            const int b0r = m0 + wm * 32 + mt * 16 + g;
            const int b1r = b0r + 8;
#pragma unroll
            for (int nt = 0; nt < 8; nt++) {
                float i0 = acc[mt][nt][0], f0 = acc[mt][nt][1];
                float i1 = acc[mt][nt][2], f1 = acc[mt][nt][3];
                float o0 = __shfl_xor_sync(~0u, i0, 1);
                float g0 = __shfl_xor_sync(~0u, f0, 1);
                float o1 = __shfl_xor_sync(~0u, i1, 1);
                float g1 = __shfl_xor_sync(~0u, f1, 1);
                if ((t & 1) == 0) {
                    const int c0 = n0 + wn * 64 + nt * 8 + 2 * t;
                    const int j = c0 >> 2;
                    if (j < HH) {
                        size_t i00 = ((size_t)b0r * NU + z) * HH + j;
                        size_t i10 = ((size_t)b1r * NU + z) * HH + j;
                        size_t h00 = ((size_t)z * BB + b0r) * KP_H + j;
                        size_t h10 = ((size_t)z * BB + b1r) * KP_H + j;
                        float mk0 = S[b0r * NU + z], mk1 = S[b1r * NU + z];
                        float cp0 = E1[i00], cp1 = E1[i10];
                        float c0v = cp0 * sigf(f0) + sigf(i0) * tanhf(g0);
                        float c1v = cp1 * sigf(f1) + sigf(i1) * tanhf(g1);
                        float h0v = sigf(o0) * tanhf(c0v);
                        float h1v = sigf(o1) * tanhf(c1v);
                        hb[i00] = h0v;  hb[i10] = h1v;
                        X2[i00] = (mk0 > 0.5f) ? c0v : cp0;
                        X2[i10] = (mk1 > 0.5f) ? c1v : cp1;
                        X3[h00] = __float2half_rn(h0v);
                        X3[h10] = __float2half_rn(h1v);
                    }
                }
            }
        }
        return;
    }

    if (EPI == 6) {
        float* out = (float*)Cv;
#pragma unroll
        for (int mt = 0; mt < 2; mt++) {
            const int r0 = m0 + wm * 32 + mt * 16 + g;
            const int r1 = r0 + 8;
            const bool v0 = r0 < cntz, v1 = r1 < cntz;
            const int b0 = v0 ? IB[z * BB + r0] : 0;
            const int b1 = v1 ? IB[z * BB + r1] : 0;
            const size_t base0 = ((size_t)b0 * NU + z) * HH;
            const size_t base1 = ((size_t)b1 * NU + z) * HH;
#pragma unroll
            for (int nt = 0; nt < 8; nt++) {
                const int n = n0 + wn * 64 + nt * 8 + 2 * t;
                if (n < Nreal) {
                    if (v0) {
                        float2 o = *(const float2*)(E1 + base0 + n);
                        float2 v = make_float2(acc[mt][nt][0] + o.x, acc[mt][nt][1] + o.y);
                        *(float2*)(out + base0 + n) = v;
                    }
                    if (v1) {
                        float2 o = *(const float2*)(E1 + base1 + n);
                        float2 v = make_float2(acc[mt][nt][2] + o.x, acc[mt][nt][3] + o.y);
                        *(float2*)(out + base1 + n) = v;
                    }
                }
            }
        }
        return;
    }

    // EPI 4: fp16 store
#pragma unroll
    for (int mt = 0; mt < 2; mt++) {
        const int r0 = m0 + wm * 32 + mt * 16 + g;
        const int r1 = r0 + 8;
        __half* h0row = (__half*)Cv + (size_t)r0 * ldc + (size_t)z * sC;
        __half* h1row = (__half*)Cv + (size_t)r1 * ldc + (size_t)z * sC;
#pragma unroll
        for (int nt = 0; nt < 8; nt++) {
            const int n = n0 + wn * 64 + nt * 8 + 2 * t;
            if (n < Nreal) {
                *(__half2*)(h0row + n) = __floats2half2_rn(acc[mt][nt][0], acc[mt][nt][1]);
                *(__half2*)(h1row + n) = __floats2half2_rn(acc[mt][nt][2], acc[mt][nt][3]);
            }
        }
    }
}

// ------------------------- unified xk + qry SIMT GEMM (fp32 mask path, BK=16) -------------------------
__global__ void __launch_bounds__(256)
xkqry_simt(const float* __restrict__ x, const float* __restrict__ hs,
           const float* __restrict__ Wk, const float* __restrict__ Wq,
           float* __restrict__ xk, float* __restrict__ qry)
{
    __shared__ __align__(16) float As[16][64];
    __shared__ __align__(16) float Bs[16][64];
    const int z = blockIdx.z;
    const float* A; int lda; const float* W; float* C; int ldc;
    if (z < NU) {
        A = hs + z * HH; lda = NU * HH;
        W = Wq + (size_t)z * HH * KD;
        C = qry + z * KD; ldc = NU * KD;
    } else {
        A = x; lda = IND; W = Wk; C = xk; ldc = KD;
    }
    const int tid = threadIdx.x;
    const int tx = tid & 15, ty = tid >> 4;
    const int m0 = blockIdx.y * 64;
    float acc[4][4];
#pragma unroll
    for (int i = 0; i < 4; i++)
#pragma unroll
        for (int j = 0; j < 4; j++) acc[i][j] = 0.f;
    const int ar = tid >> 2, ac = (tid & 3) * 4;   // 64 rows x 16 cols
    const int wr = tid >> 4, wc = (tid & 15) * 4;  // 16 rows x 64 cols
    for (int k0 = 0; k0 < 608; k0 += 16) {
        __syncthreads();
        {
            float4 v = make_float4(0.f, 0.f, 0.f, 0.f);
            if (k0 + ac < 600)
                v = *(const float4*)(A + (size_t)(m0 + ar) * lda + k0 + ac);
            As[ac][ar] = v.x; As[ac + 1][ar] = v.y; As[ac + 2][ar] = v.z; As[ac + 3][ar] = v.w;
        }
        {
            float4 v = make_float4(0.f, 0.f, 0.f, 0.f);
            if (k0 + wr < 600)
                v = *(const float4*)(W + (size_t)(k0 + wr) * KD + wc);
            *(float4*)&Bs[wr][wc] = v;
        }
        __syncthreads();
#pragma unroll
        for (int kk = 0; kk < 16; kk++) {
            float af[4], bf[4];
            *(float4*)af = *(const float4*)&As[kk][ty * 4];
            *(float4*)bf = *(const float4*)&Bs[kk][tx * 4];
#pragma unroll
            for (int i = 0; i < 4; i++)
#pragma unroll
                for (int j = 0; j < 4; j++) acc[i][j] = fmaf(af[i], bf[j], acc[i][j]);
        }
    }
#pragma unroll
    for (int i = 0; i < 4; i++) {
        float4 v;
        v.x = acc[i][0]; v.y = acc[i][1]; v.z = acc[i][2]; v.w = acc[i][3];
        *(float4*)(C + (size_t)(m0 + ty * 4 + i) * ldc + tx * 4) = v;
    }
}

// ------------------- merged weight transpose (all segments, one launch) -------------------
__global__ void __launch_bounds__(256)
wtrans_all(const float* __restrict__ Wi2h, const float* __restrict__ Wh2h,
           const float* __restrict__ Wcv, const float* __restrict__ Wco,
           const float* __restrict__ Wck, const float* __restrict__ Wcq,
           const float* __restrict__ Wv,
           __half* __restrict__ w12h, __half* __restrict__ wcvq, __half* __restrict__ w4h,
           __half* __restrict__ wv16)
{
    __shared__ float tt[64][33];
    int L = blockIdx.x;
    const float* W; __half* Oh;
    int Kreal, Nreal, Kp, Np, koff, perm, klim, gx, gy;
    if (L < 3150)       { W = Wi2h; Oh = w12h; Kreal = 400;  Nreal = 2400; Kp = KP_PRE; Np = NP_BIG; koff = 0;      perm = 1; klim = KOFF_H; gx = 7;  gy = 75; }
    else if (L < 7650)  { L -= 3150;  W = Wh2h; Oh = w12h; Kreal = 600;  Nreal = 2400; Kp = KP_PRE; Np = NP_BIG; koff = KOFF_H; perm = 1; klim = 608;  gx = 10; gy = 75; }
    else if (L < 12150) { L -= 7650;  W = Wcv;  Oh = wcvq; Kreal = 600;  Nreal = 2400; Kp = KP_H;   Np = NP_CVQ; koff = 0;      perm = 0; klim = 608;  gx = 10; gy = 75; }
    else if (L < 16482) { L -= 12150; W = Wco;  Oh = w4h;  Kreal = 2400; Nreal = 600;  Kp = KP_CTX; Np = NP_H;   koff = 0;      perm = 0; klim = 2400; gx = 38; gy = 19; }
    else if (L < 16722) { L -= 16482; W = Wck;  Oh = wcvq + (size_t)CK_OFF * KP_H; Kreal = 600; Nreal = 128; Kp = KP_H; Np = NP_CVQ; koff = 0; perm = 0; klim = 608; gx = 10; gy = 4; }
    else if (L < 16962) { L -= 16722; W = Wcq;  Oh = wcvq + (size_t)CQ_OFF * KP_H; Kreal = 600; Nreal = 128; Kp = KP_H; Np = NP_CVQ; koff = 0; perm = 0; klim = 608; gx = 10; gy = 4; }
    else                { L -= 16962; W = Wv;   Oh = wv16; Kreal = 600;  Nreal = 400;  Kp = KP_X;   Np = NP_V;   koff = 0;      perm = 0; klim = 608;  gx = 10; gy = 13; }
    const int seg = gx * gy;
    const int u = L / seg, rem = L % seg;
    const int kb = (rem % gx) * 64, nb = (rem / gx) * 32;
    const float* Wu = W + (size_t)u * Kreal * Nreal;
    const int tx = threadIdx.x & 31, ty = threadIdx.x >> 5;  // 32 x 8
#pragma unroll
    for (int yy = ty; yy < 64; yy += 8) {
        int k = kb + yy, n = nb + tx;
        tt[yy][tx] = (k < Kreal && n < Nreal) ? Wu[(size_t)k * Nreal + n] : 0.f;
    }
    __syncthreads();
    __half* OhU = Oh + (size_t)u * Np * Kp + (size_t)koff;
#pragma unroll
    for (int yy = ty; yy < 32; yy += 8) {
        int n = nb + yy;
        int k = kb + 2 * tx;
        if (k + 1 < klim) {
            int pn = perm ? ((n % 600) * 4 + n / 600) : n;
            __half2 v = __floats2half2_rn(tt[2 * tx][yy], tt[2 * tx + 1][yy]);
            *(__half2*)(OhU + (size_t)pn * Kp + k) = v;
        }
    }
}

// ------------------- x -> fp16 padded -------------------
__global__ void conv_x(const float* __restrict__ x, __half* __restrict__ o)
{
    int idx = blockIdx.x * blockDim.x + threadIdx.x;
    if (idx >= BB * KP_X) return;
    int k = idx % KP_X, b = idx / KP_X;
    o[idx] = __float2half_rn(k < IND ? x[(size_t)b * IND + k] : 0.f);
}

// ------------------- A_pre = [scale*xv | hs] fp16 (half2 vectorized) -------------------
__global__ void conv_pre(const __half* __restrict__ xv, const float* __restrict__ hs,
                         const float* __restrict__ scale, __half* __restrict__ oh)
{
    size_t idx = (size_t)blockIdx.x * blockDim.x + threadIdx.x;
    const size_t HALF_K = KP_PRE / 2;
    if (idx >= (size_t)NU * BB * HALF_K) return;
    int k = (int)(idx % HALF_K) * 2;
    int b = (int)((idx / HALF_K) % BB);
    int u = (int)(idx / (HALF_K * BB));
    float v0 = 0.f, v1 = 0.f;
    if (k < VDD) {
        float sc = scale[b * NU + u];
        __half2 xp = *(const __half2*)(xv + (size_t)b * VDD + k);
        float2 xf = __half22float2(xp);
        v0 = sc * xf.x; v1 = sc * xf.y;
    } else if (k >= KOFF_H && k < KOFF_H + HH) {
        float2 hf = *(const float2*)(hs + (size_t)b * (NU * HH) + u * HH + (k - KOFF_H));
        v0 = hf.x; v1 = hf.y;
    }
    *(__half2*)(oh + idx * 2) = __floats2half2_rn(v0, v1);
}

// ------------------- zero counters -------------------
__global__ void zero_cnt(int* cnt)
{
    if (threadIdx.x < NU) cnt[threadIdx.x] = 0;
}

// ------------------- score + top-k + compaction lists -------------------
__global__ void score_topk(const float* __restrict__ qry, const float* __restrict__ xk,
                           float* __restrict__ scale, float* __restrict__ mask,
                           int* __restrict__ cnt, int* __restrict__ posmap,
                           int* __restrict__ blist)
{
    int gw = (blockIdx.x * blockDim.x + threadIdx.x) >> 5;
    int lane = threadIdx.x & 31;
    if (gw >= BB) return;
    int b = gw;
    float xk0 = xk[b * 64 + lane], xk1 = xk[b * 64 + 32 + lane];
    float s[NU];
#pragma unroll
    for (int u = 0; u < NU; u++) {
        const float* q = qry + b * (NU * 64) + u * 64;
        float v = q[lane] * xk0 + q[32 + lane] * xk1;
#pragma unroll
        for (int o = 16; o; o >>= 1) v += __shfl_xor_sync(~0u, v, o);
        s[u] = v * 0.125f;
    }
    if (lane == 0) {
#pragma unroll
        for (int u = 0; u < NU; u++) {
            int c = 0;
#pragma unroll
            for (int v = 0; v < NU; v++)
                if (s[v] > s[u] || (s[v] == s[u] && v < u)) c++;
            float m = (c < 4) ? 1.f : 0.f;
            mask[b * NU + u] = m;
            scale[b * NU + u] = m / (1.f + expf(-s[u]));
            if (m > 0.5f) {
                int p = atomicAdd(&cnt[u], 1);
                blist[u * BB + p] = b;
                posmap[b * NU + u] = p;
            } else {
                posmap[b * NU + u] = -1;
            }
        }
    }
}

// ------------------- comm attention + inactive hs copy (half2/float4 vectorized) -------------------
__global__ void __launch_bounds__(256)
comm_attn(const __half* __restrict__ cvq, const float* __restrict__ mask,
          const int* __restrict__ posmap, const float* __restrict__ hs,
          float* __restrict__ hs_out, __half* __restrict__ cxc)
{
    int b = blockIdx.x;
    __shared__ float s_ck[NU * 128], s_cq[NU * 128];
    __shared__ float s_sc[NU][4][NU];
    __shared__ float s_pr[NU][4][8];
    __shared__ int s_pos[NU];
    int t = threadIdx.x;
    const __half* base = cvq + (size_t)b * (NU * NP_CVQ);
    for (int i = t; i < NU * 64; i += 256) {
        int m = i >> 6, c = (i & 63) * 2;
        float2 k2 = __half22float2(*(const __half2*)(base + m * NP_CVQ + CK_OFF + c));
        float2 q2 = __half22float2(*(const __half2*)(base + m * NP_CVQ + CQ_OFF + c));
        s_ck[m * 128 + c] = k2.x; s_ck[m * 128 + c + 1] = k2.y;
        s_cq[m * 128 + c] = q2.x; s_cq[m * 128 + c + 1] = q2.y;
    }
    if (t < NU) s_pos[t] = posmap[b * NU + t];
    __syncthreads();

    int w = t >> 5, lane = t & 31;
    for (int p = w; p < NU * 4 * NU; p += 8) {
        int uq = p / 24, rem = p % 24, hh = rem / 6, m = rem % 6;
        float v = s_cq[uq * 128 + hh * 32 + lane] * s_ck[m * 128 + hh * 32 + lane];
#pragma unroll
        for (int o = 16; o; o >>= 1) v += __shfl_xor_sync(~0u, v, o);
        if (lane == 0) s_sc[uq][hh][m] = v * 0.17677669529663687f;
    }
    __syncthreads();

    if (t < NU * 4) {
        int uq = t >> 2, hh = t & 3;
        float mx = -1e30f;
#pragma unroll
        for (int m = 0; m < NU; m++) mx = fmaxf(mx, s_sc[uq][hh][m]);
        float e[NU], sum = 0.f;
#pragma unroll
        for (int m = 0; m < NU; m++) { e[m] = expf(s_sc[uq][hh][m] - mx); sum += e[m]; }
        float inv = mask[b * NU + uq] / sum;
#pragma unroll
        for (int m = 0; m < NU; m++) s_pr[uq][hh][m] = e[m] * inv;
    }
    __syncthreads();

    for (int i2 = t; i2 < 1200; i2 += 256) {
        int i = i2 * 2;
        int hh = i / 600;
        float2 c[NU];
#pragma unroll
        for (int m = 0; m < NU; m++)
            c[m] = __half22float2(*(const __half2*)(base + m * NP_CVQ + i));
#pragma unroll
        for (int uq = 0; uq < NU; uq++) {
            int pos = s_pos[uq];
            if (pos >= 0) {
                float a0 = 0.f, a1 = 0.f;
#pragma unroll
                for (int m = 0; m < NU; m++) {
                    float pr = s_pr[uq][hh][m];
                    a0 += pr * c[m].x;
                    a1 += pr * c[m].y;
                }
                *(__half2*)(cxc + ((size_t)uq * BB + pos) * KP_CTX + i) =
                    __floats2half2_rn(a0, a1);
            }
        }
    }

#pragma unroll
    for (int uq = 0; uq < NU; uq++) {
        if (s_pos[uq] < 0) {
            const float4* src = (const float4*)(hs + ((size_t)b * NU + uq) * HH);
            float4* dst = (float4*)(hs_out + ((size_t)b * NU + uq) * HH);
            for (int i = t; i < 150; i += 256) dst[i] = src[i];
        }
    }
}

// ------------------------- launch -------------------------
extern "C" void kernel_launch(void* const* d_in, const int* in_sizes, int n_in,
                              void* d_out, int out_size)
{
    const float* x    = (const float*)d_in[0];
    const float* hs   = (const float*)d_in[1];
    const float* cs   = (const float*)d_in[2];
    const float* Wk   = (const float*)d_in[3];
    const float* Wv   = (const float*)d_in[4];
    const float* Wq   = (const float*)d_in[5];
    const float* Wi2h = (const float*)d_in[6];
    const float* Wh2h = (const float*)d_in[7];
    const float* Wck  = (const float*)d_in[8];
    const float* Wcq  = (const float*)d_in[9];
    const float* Wcv  = (const float*)d_in[10];
    const float* Wco  = (const float*)d_in[11];

    float* hs_out = (float*)d_out;
    float* cs_out = hs_out + (size_t)BB * NU * HH;

    float *xk, *qry, *scale, *mask, *hb;
    int *cnt, *posmap, *blist;
    __half *xvh, *cvq, *aph, *hbh, *cxc, *x16, *w12h, *wcvq, *w4h, *wv16;
    cudaGetSymbolAddress((void**)&xk, g_xk);
    cudaGetSymbolAddress((void**)&qry, g_qry);     cudaGetSymbolAddress((void**)&scale, g_scale);
    cudaGetSymbolAddress((void**)&mask, g_mask);   cudaGetSymbolAddress((void**)&hb, g_hb);
    cudaGetSymbolAddress((void**)&cnt, g_cnt);
    cudaGetSymbolAddress((void**)&posmap, g_posmap);
    cudaGetSymbolAddress((void**)&blist, g_blist);
    cudaGetSymbolAddress((void**)&xvh, g_xvh);
    cudaGetSymbolAddress((void**)&cvq, g_cvq);
    cudaGetSymbolAddress((void**)&aph, g_aph);
    cudaGetSymbolAddress((void**)&hbh, g_hbh);
    cudaGetSymbolAddress((void**)&cxc, g_cxc);
    cudaGetSymbolAddress((void**)&x16, g_x16);
    cudaGetSymbolAddress((void**)&w12h, g_w12h);
    cudaGetSymbolAddress((void**)&wcvq, g_wcvq);
    cudaGetSymbolAddress((void**)&w4h, g_w4h);
    cudaGetSymbolAddress((void**)&wv16, g_wv16);

    cudaFuncSetAttribute(hmma_gemm<4>, cudaFuncAttributeMaxDynamicSharedMemorySize, SMEM_DYN);
    cudaFuncSetAttribute(hmma_gemm<5>, cudaFuncAttributeMaxDynamicSharedMemorySize, SMEM_DYN);
    cudaFuncSetAttribute(hmma_gemm<6>, cudaFuncAttributeMaxDynamicSharedMemorySize, SMEM_DYN);

    static cudaStream_t s_side = nullptr;
    static cudaEvent_t s_fork = nullptr, s_join = nullptr;
    if (!s_side) {
        cudaStreamCreateWithFlags(&s_side, cudaStreamNonBlocking);
        cudaEventCreateWithFlags(&s_fork, cudaEventDisableTiming);
        cudaEventCreateWithFlags(&s_join, cudaEventDisableTiming);
    }

    cudaEventRecord(s_fork, (cudaStream_t)0);
    cudaStreamWaitEvent(s_side, s_fork, 0);

    zero_cnt<<<1, 32, 0, s_side>>>(cnt);
    xkqry_simt<<<dim3(1, 64, 7), 256, 0, s_side>>>(x, hs, Wk, Wq, xk, qry);
    score_topk<<<(BB * 32 + 255) / 256, 256, 0, s_side>>>(qry, xk, scale, mask, cnt, posmap, blist);
    cudaEventRecord(s_join, s_side);

    wtrans_all<<<17092, 256>>>(Wi2h, Wh2h, Wcv, Wco, Wck, Wcq, Wv,
                               w12h, wcvq, w4h, wv16);
    conv_x<<<(BB * KP_X + 255) / 256, 256>>>(x, x16);
    hmma_gemm<4><<<dim3(4, 32, 1), 256, SMEM_DYN>>>(
        x16, 0LL, KP_X, wv16, 0LL, xvh, VDD, 0, VDD,
        nullptr, nullptr, nullptr, nullptr, nullptr, nullptr);

    cudaStreamWaitEvent((cudaStream_t)0, s_join, 0);

    conv_pre<<<(int)(((size_t)NU * BB * (KP_PRE / 2) + 255) / 256), 256>>>(xvh, hs, scale, aph);

    // preact GEMM + fused LSTM epilogue -> hb, hbh, cs_out
    hmma_gemm<5><<<dim3(19, 32, NU), 256, SMEM_DYN>>>(
        aph, (long long)BB * KP_PRE, KP_PRE, w12h, (long long)NP_BIG * KP_PRE,
        hb, 0, 0, 2400, mask, cs, cs_out, hbh, nullptr, nullptr);

    // cv | ck | cq combined (N=2688, fp16 out)
    hmma_gemm<4><<<dim3(21, 32, NU), 256, SMEM_DYN>>>(
        hbh, (long long)BB * KP_H, KP_H, wcvq, (long long)NP_CVQ * KP_H,
        cvq, NU * NP_CVQ, NP_CVQ, NP_CVQ, nullptr, nullptr, nullptr, nullptr, nullptr, nullptr);

    // comm attention (+ inactive hs copy)
    comm_attn<<<BB, 256>>>(cvq, mask, posmap, hs, hs_out, cxc);

    // hs_out (active rows only) = ctx_compact @ Wco + hb, scattered by blist
    hmma_gemm<6><<<dim3(5, 32, NU), 256, SMEM_DYN>>>(
        cxc, (long long)BB * KP_CTX, KP_CTX, w4h, (long long)NP_H * KP_CTX,
        hs_out, 0, 0, HH, nullptr, hb, nullptr, nullptr, blist, cnt);

    (void)in_sizes; (void)n_in; (void)out_size;
}